// round 4
// baseline (speedup 1.0000x reference)
#include <cuda_runtime.h>
#include <math.h>

#define N_NODES 100000
#define N_EDGES 3200000
#define IN_DIM  500
#define HID     64
#define OUT_DIM 40
#define K_STEPS 10

// ---------------- device scratch (static: no allocations allowed) -------------
__device__ int   g_counts[N_NODES];
__device__ float g_dinv[N_NODES];
__device__ int   g_ptr[N_NODES + 1];
__device__ int   g_cursor[N_NODES];
__device__ __align__(16) int2  g_edges[N_EDGES];   // (src, norm-bits), sorted by dst
__device__ __align__(16) float g_h0[(size_t)N_NODES * HID];
__device__ __align__(16) float g_hA[(size_t)N_NODES * HID];
__device__ __align__(16) float g_hB[(size_t)N_NODES * HID];

// selector: 0 -> h0, 1 -> hA, 2 -> hB  (avoids cudaGetSymbolAddress on host)
__device__ __forceinline__ float* hbuf(int s) {
    return (s == 0) ? g_h0 : ((s == 1) ? g_hA : g_hB);
}

// ---------------- f32x2 packed-FMA helpers -----------------------------------
#define FMA2(acc, a, b) \
    asm("fma.rn.f32x2 %0, %1, %2, %0;" : "+l"(acc) : "l"(a), "l"(b))
#define PACK_DUP(dst, x) \
    asm("mov.b64 %0, {%1, %1};" : "=l"(dst) : "f"(x))
#define UNPACK2(lo, hi, v) \
    asm("mov.b64 {%0, %1}, %2;" : "=f"(lo), "=f"(hi) : "l"(v))

// ---------------- CSR build ---------------------------------------------------
__global__ void k_zero_counts() {
    int i = blockIdx.x * blockDim.x + threadIdx.x;
    if (i < N_NODES) g_counts[i] = 0;
}

__global__ void k_count(const int* __restrict__ col) {
    int e = blockIdx.x * blockDim.x + threadIdx.x;
    if (e < N_EDGES) atomicAdd(&g_counts[col[e]], 1);
}

__global__ void k_dinv() {
    int i = blockIdx.x * blockDim.x + threadIdx.x;
    if (i < N_NODES) g_dinv[i] = rsqrtf((float)(g_counts[i] + 1)); // +1 self loop
}

// single-block exclusive scan over 100k counts -> ptr, cursor
__global__ void k_scan() {
    __shared__ int sums[1024];
    const int t = threadIdx.x;
    const int chunk = (N_NODES + 1023) / 1024;   // 98
    int beg = t * chunk;
    int end = min(beg + chunk, N_NODES);
    int s = 0;
    for (int i = beg; i < end; i++) s += g_counts[i];
    sums[t] = s;
    __syncthreads();
    for (int off = 1; off < 1024; off <<= 1) {
        int v = (t >= off) ? sums[t - off] : 0;
        __syncthreads();
        sums[t] += v;
        __syncthreads();
    }
    int run = (t == 0) ? 0 : sums[t - 1];
    for (int i = beg; i < end; i++) {
        g_ptr[i]    = run;
        g_cursor[i] = run;
        run += g_counts[i];
    }
    if (t == 1023) g_ptr[N_NODES] = sums[1023];
}

__global__ void k_scatter(const int* __restrict__ ei) {
    int e = blockIdx.x * blockDim.x + threadIdx.x;
    if (e >= N_EDGES) return;
    int r = ei[e];               // src (row)
    int c = ei[N_EDGES + e];     // dst (col)
    float nrm = g_dinv[r] * g_dinv[c];
    int pos = atomicAdd(&g_cursor[c], 1);
    g_edges[pos] = make_int2(r, __float_as_int(nrm));
}

// ---------------- lin1: h0 = x @ W1 + b1  (f32x2 packed FMA) ------------------
// thread-per-row, 256 rows/block; W1/x chunked through SMEM (K-chunk = 32)
__global__ void __launch_bounds__(256) k_gemm1(const float* __restrict__ x,
                                               const float* __restrict__ W1,
                                               const float* __restrict__ b1) {
    __shared__ __align__(16) float Ws[32 * 64];     // 8 KB
    __shared__ float xs[256 * 33];                  // 33 KB, padded stride
    __shared__ __align__(16) float bs[64];

    const int tid = threadIdx.x;
    const int row = blockIdx.x * 256 + tid;

    if (tid < 16) {
        *(float4*)&bs[tid * 4] = *(const float4*)&b1[tid * 4];
    }
    __syncthreads();

    unsigned long long acc[32];
#pragma unroll
    for (int p = 0; p < 32; p++)
        acc[p] = *(const unsigned long long*)&bs[2 * p];

    for (int kc = 0; kc < IN_DIM; kc += 32) {
        __syncthreads();
        // stage W1 chunk: 32 x 64 floats = 512 float4
        for (int i = tid; i < 512; i += 256) {
            int kk = i >> 4, j4 = i & 15;
            float4 v = make_float4(0.f, 0.f, 0.f, 0.f);
            if (kc + kk < IN_DIM)
                v = *(const float4*)&W1[(size_t)(kc + kk) * HID + j4 * 4];
            *(float4*)&Ws[kk * 64 + j4 * 4] = v;
        }
        // stage x chunk: 256 rows x 32 cols = 2048 float4
        for (int i = tid; i < 2048; i += 256) {
            int r  = i >> 3;
            int c4 = i & 7;
            int col = kc + c4 * 4;
            int grow = blockIdx.x * 256 + r;
            if (grow >= N_NODES) grow = N_NODES - 1;
            float4 v = make_float4(0.f, 0.f, 0.f, 0.f);
            if (col < IN_DIM)
                v = *(const float4*)&x[(size_t)grow * IN_DIM + col];
            float* d = &xs[r * 33 + c4 * 4];
            d[0] = v.x; d[1] = v.y; d[2] = v.z; d[3] = v.w;
        }
        __syncthreads();

#pragma unroll 2
        for (int kk = 0; kk < 32; kk++) {
            float xv = xs[tid * 33 + kk];
            unsigned long long xv2;
            PACK_DUP(xv2, xv);
            const ulonglong2* wr = reinterpret_cast<const ulonglong2*>(&Ws[kk * 64]);
#pragma unroll
            for (int q = 0; q < 16; q++) {
                ulonglong2 w = wr[q];
                FMA2(acc[2 * q],     xv2, w.x);
                FMA2(acc[2 * q + 1], xv2, w.y);
            }
        }
    }

    if (row < N_NODES) {
#pragma unroll
        for (int q = 0; q < 16; q++) {
            float a, b, c, d;
            UNPACK2(a, b, acc[2 * q]);
            UNPACK2(c, d, acc[2 * q + 1]);
            *(float4*)&g_h0[(size_t)row * HID + q * 4] = make_float4(a, b, c, d);
        }
    }
}

// ---------------- APPNP propagation step (warp-per-node CSR gather) ----------
__global__ void __launch_bounds__(256) k_prop(int sin_sel, int sout_sel) {
    const float* __restrict__ xin = hbuf(sin_sel);
    float* __restrict__ xout = hbuf(sout_sel);

    int node = (blockIdx.x * blockDim.x + threadIdx.x) >> 5;
    int lane = threadIdx.x & 31;
    if (node >= N_NODES) return;

    int beg = g_ptr[node];
    int end = g_ptr[node + 1];

    float ax = 0.f, ay = 0.f;
    for (int base = beg; base < end; base += 32) {
        int idx = base + lane;
        int2 ed = (idx < end) ? g_edges[idx] : make_int2(0, 0);
        int cnt = min(32, end - base);
        for (int j = 0; j < cnt; j++) {
            int   src = __shfl_sync(0xffffffffu, ed.x, j);
            float nrm = __int_as_float(__shfl_sync(0xffffffffu, ed.y, j));
            float2 v = *(const float2*)(xin + (size_t)src * HID + lane * 2);
            ax = fmaf(nrm, v.x, ax);
            ay = fmaf(nrm, v.y, ay);
        }
    }
    // self loop
    float dv = g_dinv[node];
    float sn = dv * dv;
    float2 vs = *(const float2*)(xin + (size_t)node * HID + lane * 2);
    ax = fmaf(sn, vs.x, ax);
    ay = fmaf(sn, vs.y, ay);

    float2 h0v = *(const float2*)(g_h0 + (size_t)node * HID + lane * 2);
    float2 o;
    o.x = 0.9f * ax + 0.1f * h0v.x;
    o.y = 0.9f * ay + 0.1f * h0v.y;
    *(float2*)(xout + (size_t)node * HID + lane * 2) = o;
}

// ---------------- BN + lin2 + log_softmax (fused epilogue) --------------------
__global__ void __launch_bounds__(128) k_epilogue(int h_sel,
                                                  const float* __restrict__ gamma,
                                                  const float* __restrict__ beta,
                                                  const float* __restrict__ mean,
                                                  const float* __restrict__ var,
                                                  const float* __restrict__ W2,
                                                  const float* __restrict__ b2,
                                                  float* __restrict__ out) {
    const float* __restrict__ h = hbuf(h_sel);

    __shared__ float sc[HID], sh[HID];
    __shared__ float W2s[HID * OUT_DIM];
    __shared__ float b2s[OUT_DIM];

    const int tid = threadIdx.x;
    if (tid < HID) {
        float s = gamma[tid] * rsqrtf(var[tid] + 1e-5f);
        sc[tid] = s;
        sh[tid] = beta[tid] - mean[tid] * s;
    }
    if (tid < OUT_DIM) b2s[tid] = b2[tid];
    for (int i = tid; i < HID * OUT_DIM; i += 128) W2s[i] = W2[i];
    __syncthreads();

    int node = blockIdx.x * 128 + tid;
    if (node >= N_NODES) return;

    float acc[OUT_DIM];
#pragma unroll
    for (int j = 0; j < OUT_DIM; j++) acc[j] = b2s[j];

    const float* hp = h + (size_t)node * HID;
    for (int k = 0; k < HID; k++) {
        float t = fmaf(hp[k], sc[k], sh[k]);
#pragma unroll
        for (int j = 0; j < OUT_DIM; j++)
            acc[j] = fmaf(t, W2s[k * OUT_DIM + j], acc[j]);
    }

    float m = acc[0];
#pragma unroll
    for (int j = 1; j < OUT_DIM; j++) m = fmaxf(m, acc[j]);
    float s = 0.f;
#pragma unroll
    for (int j = 0; j < OUT_DIM; j++) s += expf(acc[j] - m);
    float lse = m + logf(s);

    float* op = out + (size_t)node * OUT_DIM;                              // log_softmax
    float* ep = out + (size_t)N_NODES * OUT_DIM + (size_t)node * OUT_DIM;  // emb
#pragma unroll
    for (int j4 = 0; j4 < OUT_DIM / 4; j4++) {
        float4 e = make_float4(acc[4*j4], acc[4*j4+1], acc[4*j4+2], acc[4*j4+3]);
        float4 o = make_float4(e.x - lse, e.y - lse, e.z - lse, e.w - lse);
        *(float4*)&op[4 * j4] = o;
        *(float4*)&ep[4 * j4] = e;
    }
}

// ---------------- host launcher -----------------------------------------------
extern "C" void kernel_launch(void* const* d_in, const int* in_sizes, int n_in,
                              void* d_out, int out_size) {
    const float* x     = (const float*)d_in[0];
    const int*   ei    = (const int*)d_in[1];     // int64 inputs delivered as int32
    const float* W1    = (const float*)d_in[2];
    const float* b1    = (const float*)d_in[3];
    const float* gamma = (const float*)d_in[4];
    const float* beta  = (const float*)d_in[5];
    const float* mean  = (const float*)d_in[6];
    const float* var   = (const float*)d_in[7];
    const float* W2    = (const float*)d_in[8];
    const float* b2    = (const float*)d_in[9];
    float*       out   = (float*)d_out;

    const int nb_n = (N_NODES + 255) / 256;
    const int nb_e = (N_EDGES + 255) / 256;

    k_zero_counts<<<nb_n, 256>>>();
    k_count<<<nb_e, 256>>>(ei + N_EDGES);     // col = second row of edge_index
    k_dinv<<<nb_n, 256>>>();
    k_scan<<<1, 1024>>>();
    k_scatter<<<nb_e, 256>>>(ei);

    k_gemm1<<<nb_n, 256>>>(x, W1, b1);

    const int prop_blocks = (N_NODES * 32 + 255) / 256;
    int cur = 0;                               // h0
    for (int s = 0; s < K_STEPS; s++) {
        int nxt = (s & 1) ? 2 : 1;             // even step -> hA, odd -> hB
        k_prop<<<prop_blocks, 256>>>(cur, nxt);
        cur = nxt;
    }

    k_epilogue<<<(N_NODES + 127) / 128, 128>>>(cur, gamma, beta, mean, var,
                                               W2, b2, out);
}

// round 5
// speedup vs baseline: 1.6131x; 1.6131x over previous
#include <cuda_runtime.h>
#include <math.h>

#define N_NODES 100000
#define N_EDGES 3200000
#define IN_DIM  500
#define HID     64
#define OUT_DIM 40
#define K_STEPS 10
#define SCAN_TILE 1024
#define NUM_TILES ((N_NODES + SCAN_TILE - 1) / SCAN_TILE)   // 98

// ---------------- device scratch (static: no allocations allowed) -------------
__device__ int   g_counts[N_NODES];
__device__ float g_dinv[N_NODES];
__device__ int   g_ptr[N_NODES + 1];
__device__ int   g_cursor[N_NODES];
__device__ int   g_tilesum[NUM_TILES];
__device__ int   g_tileoff[NUM_TILES];
__device__ __align__(16) int2  g_edges[N_EDGES];   // (src, norm-bits), sorted by dst
__device__ __align__(16) float g_h0[(size_t)N_NODES * HID];
__device__ __align__(16) float g_hA[(size_t)N_NODES * HID];
__device__ __align__(16) float g_hB[(size_t)N_NODES * HID];

// selector: 0 -> h0, 1 -> hA, 2 -> hB  (avoids cudaGetSymbolAddress on host)
__device__ __forceinline__ float* hbuf(int s) {
    return (s == 0) ? g_h0 : ((s == 1) ? g_hA : g_hB);
}

// ---------------- f32x2 packed-FMA helpers -----------------------------------
#define FMA2(acc, a, b) \
    asm("fma.rn.f32x2 %0, %1, %2, %0;" : "+l"(acc) : "l"(a), "l"(b))
#define PACK_DUP(dst, x) \
    asm("mov.b64 %0, {%1, %1};" : "=l"(dst) : "f"(x))
#define UNPACK2(lo, hi, v) \
    asm("mov.b64 {%0, %1}, %2;" : "=f"(lo), "=f"(hi) : "l"(v))

// ---------------- CSR build ---------------------------------------------------
__global__ void k_zero_counts() {
    int i = blockIdx.x * blockDim.x + threadIdx.x;
    if (i < N_NODES) g_counts[i] = 0;
}

__global__ void k_count(const int* __restrict__ col) {
    int e = blockIdx.x * blockDim.x + threadIdx.x;
    if (e < N_EDGES) atomicAdd(&g_counts[col[e]], 1);
}

__global__ void k_dinv() {
    int i = blockIdx.x * blockDim.x + threadIdx.x;
    if (i < N_NODES) g_dinv[i] = rsqrtf((float)(g_counts[i] + 1)); // +1 self loop
}

// --- parallel 3-phase exclusive scan of g_counts -> g_ptr / g_cursor ---------
// phase A: per-tile (1024-wide) block scan, tile-local exclusive into g_ptr
__global__ void __launch_bounds__(SCAN_TILE) k_scanA() {
    __shared__ int s[SCAN_TILE];
    const int t = threadIdx.x;
    const int gid = blockIdx.x * SCAN_TILE + t;
    int v = (gid < N_NODES) ? g_counts[gid] : 0;
    s[t] = v;
    __syncthreads();
#pragma unroll
    for (int off = 1; off < SCAN_TILE; off <<= 1) {
        int u = (t >= off) ? s[t - off] : 0;
        __syncthreads();
        s[t] += u;
        __syncthreads();
    }
    if (gid < N_NODES) g_ptr[gid] = s[t] - v;      // exclusive, tile-local
    if (t == SCAN_TILE - 1) g_tilesum[blockIdx.x] = s[t];
}

// phase B: one small block scans the 98 tile sums (exclusive)
__global__ void __launch_bounds__(128) k_scanB() {
    __shared__ int s[128];
    const int t = threadIdx.x;
    int v = (t < NUM_TILES) ? g_tilesum[t] : 0;
    s[t] = v;
    __syncthreads();
#pragma unroll
    for (int off = 1; off < 128; off <<= 1) {
        int u = (t >= off) ? s[t - off] : 0;
        __syncthreads();
        s[t] += u;
        __syncthreads();
    }
    if (t < NUM_TILES) g_tileoff[t] = s[t] - v;
}

// phase C: add tile offsets, mirror into cursor, set sentinel
__global__ void k_scanC() {
    int i = blockIdx.x * blockDim.x + threadIdx.x;
    if (i < N_NODES) {
        int p = g_ptr[i] + g_tileoff[i >> 10];
        g_ptr[i] = p;
        g_cursor[i] = p;
    }
    if (i == 0) g_ptr[N_NODES] = N_EDGES;
}

__global__ void k_scatter(const int* __restrict__ ei) {
    int e = blockIdx.x * blockDim.x + threadIdx.x;
    if (e >= N_EDGES) return;
    int r = ei[e];               // src (row)
    int c = ei[N_EDGES + e];     // dst (col)
    float nrm = g_dinv[r] * g_dinv[c];
    int pos = atomicAdd(&g_cursor[c], 1);
    g_edges[pos] = make_int2(r, __float_as_int(nrm));
}

// ---------------- lin1: h0 = x @ W1 + b1  (f32x2 packed FMA) ------------------
__global__ void __launch_bounds__(256) k_gemm1(const float* __restrict__ x,
                                               const float* __restrict__ W1,
                                               const float* __restrict__ b1) {
    __shared__ __align__(16) float Ws[32 * 64];     // 8 KB
    __shared__ float xs[256 * 33];                  // 33 KB, padded stride
    __shared__ __align__(16) float bs[64];

    const int tid = threadIdx.x;
    const int row = blockIdx.x * 256 + tid;

    if (tid < 16) {
        *(float4*)&bs[tid * 4] = *(const float4*)&b1[tid * 4];
    }
    __syncthreads();

    unsigned long long acc[32];
#pragma unroll
    for (int p = 0; p < 32; p++)
        acc[p] = *(const unsigned long long*)&bs[2 * p];

    for (int kc = 0; kc < IN_DIM; kc += 32) {
        __syncthreads();
        for (int i = tid; i < 512; i += 256) {
            int kk = i >> 4, j4 = i & 15;
            float4 v = make_float4(0.f, 0.f, 0.f, 0.f);
            if (kc + kk < IN_DIM)
                v = *(const float4*)&W1[(size_t)(kc + kk) * HID + j4 * 4];
            *(float4*)&Ws[kk * 64 + j4 * 4] = v;
        }
        for (int i = tid; i < 2048; i += 256) {
            int r  = i >> 3;
            int c4 = i & 7;
            int col = kc + c4 * 4;
            int grow = blockIdx.x * 256 + r;
            if (grow >= N_NODES) grow = N_NODES - 1;
            float4 v = make_float4(0.f, 0.f, 0.f, 0.f);
            if (col < IN_DIM)
                v = *(const float4*)&x[(size_t)grow * IN_DIM + col];
            float* d = &xs[r * 33 + c4 * 4];
            d[0] = v.x; d[1] = v.y; d[2] = v.z; d[3] = v.w;
        }
        __syncthreads();

#pragma unroll 2
        for (int kk = 0; kk < 32; kk++) {
            float xv = xs[tid * 33 + kk];
            unsigned long long xv2;
            PACK_DUP(xv2, xv);
            const ulonglong2* wr = reinterpret_cast<const ulonglong2*>(&Ws[kk * 64]);
#pragma unroll
            for (int q = 0; q < 16; q++) {
                ulonglong2 w = wr[q];
                FMA2(acc[2 * q],     xv2, w.x);
                FMA2(acc[2 * q + 1], xv2, w.y);
            }
        }
    }

    if (row < N_NODES) {
#pragma unroll
        for (int q = 0; q < 16; q++) {
            float a, b, c, d;
            UNPACK2(a, b, acc[2 * q]);
            UNPACK2(c, d, acc[2 * q + 1]);
            *(float4*)&g_h0[(size_t)row * HID + q * 4] = make_float4(a, b, c, d);
        }
    }
}

// ---------------- APPNP propagation step (warp-per-node CSR gather) ----------
// Full 32-edge batches fully unrolled (x4 groups, 4 accumulator pairs) for MLP;
// short remainder handled with the dynamic loop.
__global__ void __launch_bounds__(256) k_prop(int sin_sel, int sout_sel) {
    const float* __restrict__ xin = hbuf(sin_sel);
    float* __restrict__ xout = hbuf(sout_sel);

    int node = (blockIdx.x * blockDim.x + threadIdx.x) >> 5;
    int lane = threadIdx.x & 31;
    if (node >= N_NODES) return;

    const int beg = g_ptr[node];
    const int end = g_ptr[node + 1];
    const int deg = end - beg;
    const int nfull = deg & ~31;

    float a0x = 0.f, a0y = 0.f, a1x = 0.f, a1y = 0.f;
    float a2x = 0.f, a2y = 0.f, a3x = 0.f, a3y = 0.f;

    int base = beg;
    for (; base < beg + nfull; base += 32) {
        int2 ed = g_edges[base + lane];
#pragma unroll
        for (int j = 0; j < 32; j += 4) {
            int   s0 = __shfl_sync(0xffffffffu, ed.x, j + 0);
            int   s1 = __shfl_sync(0xffffffffu, ed.x, j + 1);
            int   s2 = __shfl_sync(0xffffffffu, ed.x, j + 2);
            int   s3 = __shfl_sync(0xffffffffu, ed.x, j + 3);
            float n0 = __int_as_float(__shfl_sync(0xffffffffu, ed.y, j + 0));
            float n1 = __int_as_float(__shfl_sync(0xffffffffu, ed.y, j + 1));
            float n2 = __int_as_float(__shfl_sync(0xffffffffu, ed.y, j + 2));
            float n3 = __int_as_float(__shfl_sync(0xffffffffu, ed.y, j + 3));
            float2 v0 = *(const float2*)(xin + (size_t)s0 * HID + lane * 2);
            float2 v1 = *(const float2*)(xin + (size_t)s1 * HID + lane * 2);
            float2 v2 = *(const float2*)(xin + (size_t)s2 * HID + lane * 2);
            float2 v3 = *(const float2*)(xin + (size_t)s3 * HID + lane * 2);
            a0x = fmaf(n0, v0.x, a0x);  a0y = fmaf(n0, v0.y, a0y);
            a1x = fmaf(n1, v1.x, a1x);  a1y = fmaf(n1, v1.y, a1y);
            a2x = fmaf(n2, v2.x, a2x);  a2y = fmaf(n2, v2.y, a2y);
            a3x = fmaf(n3, v3.x, a3x);  a3y = fmaf(n3, v3.y, a3y);
        }
    }

    // remainder (< 32 edges)
    const int rem = deg - nfull;
    if (rem) {
        int idx = base + lane;
        int2 ed = (idx < end) ? g_edges[idx] : make_int2(0, 0);
        for (int j = 0; j < rem; j++) {
            int   src = __shfl_sync(0xffffffffu, ed.x, j);
            float nrm = __int_as_float(__shfl_sync(0xffffffffu, ed.y, j));
            float2 v = *(const float2*)(xin + (size_t)src * HID + lane * 2);
            a0x = fmaf(nrm, v.x, a0x);
            a0y = fmaf(nrm, v.y, a0y);
        }
    }

    float ax = (a0x + a1x) + (a2x + a3x);
    float ay = (a0y + a1y) + (a2y + a3y);

    // self loop
    float dv = g_dinv[node];
    float sn = dv * dv;
    float2 vs = *(const float2*)(xin + (size_t)node * HID + lane * 2);
    ax = fmaf(sn, vs.x, ax);
    ay = fmaf(sn, vs.y, ay);

    float2 h0v = *(const float2*)(g_h0 + (size_t)node * HID + lane * 2);
    float2 o;
    o.x = 0.9f * ax + 0.1f * h0v.x;
    o.y = 0.9f * ay + 0.1f * h0v.y;
    *(float2*)(xout + (size_t)node * HID + lane * 2) = o;
}

// ---------------- BN + lin2 + log_softmax (fused epilogue) --------------------
__global__ void __launch_bounds__(128) k_epilogue(int h_sel,
                                                  const float* __restrict__ gamma,
                                                  const float* __restrict__ beta,
                                                  const float* __restrict__ mean,
                                                  const float* __restrict__ var,
                                                  const float* __restrict__ W2,
                                                  const float* __restrict__ b2,
                                                  float* __restrict__ out) {
    const float* __restrict__ h = hbuf(h_sel);

    __shared__ float sc[HID], sh[HID];
    __shared__ float W2s[HID * OUT_DIM];
    __shared__ float b2s[OUT_DIM];

    const int tid = threadIdx.x;
    if (tid < HID) {
        float s = gamma[tid] * rsqrtf(var[tid] + 1e-5f);
        sc[tid] = s;
        sh[tid] = beta[tid] - mean[tid] * s;
    }
    if (tid < OUT_DIM) b2s[tid] = b2[tid];
    for (int i = tid; i < HID * OUT_DIM; i += 128) W2s[i] = W2[i];
    __syncthreads();

    int node = blockIdx.x * 128 + tid;
    if (node >= N_NODES) return;

    float acc[OUT_DIM];
#pragma unroll
    for (int j = 0; j < OUT_DIM; j++) acc[j] = b2s[j];

    const float* hp = h + (size_t)node * HID;
    for (int k = 0; k < HID; k++) {
        float t = fmaf(hp[k], sc[k], sh[k]);
#pragma unroll
        for (int j = 0; j < OUT_DIM; j++)
            acc[j] = fmaf(t, W2s[k * OUT_DIM + j], acc[j]);
    }

    float m = acc[0];
#pragma unroll
    for (int j = 1; j < OUT_DIM; j++) m = fmaxf(m, acc[j]);
    float s = 0.f;
#pragma unroll
    for (int j = 0; j < OUT_DIM; j++) s += expf(acc[j] - m);
    float lse = m + logf(s);

    float* op = out + (size_t)node * OUT_DIM;                              // log_softmax
    float* ep = out + (size_t)N_NODES * OUT_DIM + (size_t)node * OUT_DIM;  // emb
#pragma unroll
    for (int j4 = 0; j4 < OUT_DIM / 4; j4++) {
        float4 e = make_float4(acc[4*j4], acc[4*j4+1], acc[4*j4+2], acc[4*j4+3]);
        float4 o = make_float4(e.x - lse, e.y - lse, e.z - lse, e.w - lse);
        *(float4*)&op[4 * j4] = o;
        *(float4*)&ep[4 * j4] = e;
    }
}

// ---------------- host launcher -----------------------------------------------
extern "C" void kernel_launch(void* const* d_in, const int* in_sizes, int n_in,
                              void* d_out, int out_size) {
    const float* x     = (const float*)d_in[0];
    const int*   ei    = (const int*)d_in[1];     // int64 inputs delivered as int32
    const float* W1    = (const float*)d_in[2];
    const float* b1    = (const float*)d_in[3];
    const float* gamma = (const float*)d_in[4];
    const float* beta  = (const float*)d_in[5];
    const float* mean  = (const float*)d_in[6];
    const float* var   = (const float*)d_in[7];
    const float* W2    = (const float*)d_in[8];
    const float* b2    = (const float*)d_in[9];
    float*       out   = (float*)d_out;

    const int nb_n = (N_NODES + 255) / 256;
    const int nb_e = (N_EDGES + 255) / 256;

    k_zero_counts<<<nb_n, 256>>>();
    k_count<<<nb_e, 256>>>(ei + N_EDGES);     // col = second row of edge_index
    k_dinv<<<nb_n, 256>>>();
    k_scanA<<<NUM_TILES, SCAN_TILE>>>();
    k_scanB<<<1, 128>>>();
    k_scanC<<<nb_n, 256>>>();
    k_scatter<<<nb_e, 256>>>(ei);

    k_gemm1<<<nb_n, 256>>>(x, W1, b1);

    const int prop_blocks = (N_NODES * 32 + 255) / 256;
    int cur = 0;                               // h0
    for (int s = 0; s < K_STEPS; s++) {
        int nxt = (s & 1) ? 2 : 1;             // even step -> hA, odd -> hB
        k_prop<<<prop_blocks, 256>>>(cur, nxt);
        cur = nxt;
    }

    k_epilogue<<<(N_NODES + 127) / 128, 128>>>(cur, gamma, beta, mean, var,
                                               W2, b2, out);
}

// round 6
// speedup vs baseline: 1.7193x; 1.0658x over previous
#include <cuda_runtime.h>
#include <cuda_fp16.h>
#include <math.h>

#define N_NODES 100000
#define N_EDGES 3200000
#define IN_DIM  500
#define HID     64
#define HID2    (HID / 2)
#define OUT_DIM 40
#define K_STEPS 10
#define SCAN_TILE 1024
#define NUM_TILES ((N_NODES + SCAN_TILE - 1) / SCAN_TILE)   // 98

// ---------------- device scratch (static: no allocations allowed) -------------
__device__ int   g_counts[N_NODES];
__device__ float g_dinv[N_NODES];
__device__ int   g_ptr[N_NODES + 1];
__device__ int   g_cursor[N_NODES];
__device__ int   g_tilesum[NUM_TILES];
__device__ int   g_tileoff[NUM_TILES];
__device__ __align__(16) int2    g_edges[N_EDGES];           // (src, norm-bits), dst-sorted
__device__ __align__(16) float   g_h0[(size_t)N_NODES * HID];    // fp32 anchor
__device__ __align__(16) float   g_hf32[(size_t)N_NODES * HID];  // fp32 final (epilogue)
__device__ __align__(16) __half2 g_h16A[(size_t)N_NODES * HID2]; // fp16 ping
__device__ __align__(16) __half2 g_h16B[(size_t)N_NODES * HID2]; // fp16 pong

__device__ __forceinline__ __half2* h16buf(int s) { return s ? g_h16B : g_h16A; }

// ---------------- f32x2 packed-FMA helpers -----------------------------------
#define FMA2(acc, a, b) \
    asm("fma.rn.f32x2 %0, %1, %2, %0;" : "+l"(acc) : "l"(a), "l"(b))
#define PACK_DUP(dst, x) \
    asm("mov.b64 %0, {%1, %1};" : "=l"(dst) : "f"(x))
#define UNPACK2(lo, hi, v) \
    asm("mov.b64 {%0, %1}, %2;" : "=f"(lo), "=f"(hi) : "l"(v))

// ---------------- CSR build ---------------------------------------------------
__global__ void k_zero_counts() {
    int i = blockIdx.x * blockDim.x + threadIdx.x;
    if (i < N_NODES) g_counts[i] = 0;
}

__global__ void k_count(const int* __restrict__ col) {
    int e = blockIdx.x * blockDim.x + threadIdx.x;
    if (e < N_EDGES) atomicAdd(&g_counts[col[e]], 1);
}

__global__ void k_dinv() {
    int i = blockIdx.x * blockDim.x + threadIdx.x;
    if (i < N_NODES) g_dinv[i] = rsqrtf((float)(g_counts[i] + 1)); // +1 self loop
}

// --- parallel 3-phase exclusive scan of g_counts -> g_ptr / g_cursor ---------
__global__ void __launch_bounds__(SCAN_TILE) k_scanA() {
    __shared__ int s[SCAN_TILE];
    const int t = threadIdx.x;
    const int gid = blockIdx.x * SCAN_TILE + t;
    int v = (gid < N_NODES) ? g_counts[gid] : 0;
    s[t] = v;
    __syncthreads();
#pragma unroll
    for (int off = 1; off < SCAN_TILE; off <<= 1) {
        int u = (t >= off) ? s[t - off] : 0;
        __syncthreads();
        s[t] += u;
        __syncthreads();
    }
    if (gid < N_NODES) g_ptr[gid] = s[t] - v;      // exclusive, tile-local
    if (t == SCAN_TILE - 1) g_tilesum[blockIdx.x] = s[t];
}

__global__ void __launch_bounds__(128) k_scanB() {
    __shared__ int s[128];
    const int t = threadIdx.x;
    int v = (t < NUM_TILES) ? g_tilesum[t] : 0;
    s[t] = v;
    __syncthreads();
#pragma unroll
    for (int off = 1; off < 128; off <<= 1) {
        int u = (t >= off) ? s[t - off] : 0;
        __syncthreads();
        s[t] += u;
        __syncthreads();
    }
    if (t < NUM_TILES) g_tileoff[t] = s[t] - v;
}

__global__ void k_scanC() {
    int i = blockIdx.x * blockDim.x + threadIdx.x;
    if (i < N_NODES) {
        int p = g_ptr[i] + g_tileoff[i >> 10];
        g_ptr[i] = p;
        g_cursor[i] = p;
    }
    if (i == 0) g_ptr[N_NODES] = N_EDGES;
}

__global__ void k_scatter(const int* __restrict__ ei) {
    int e = blockIdx.x * blockDim.x + threadIdx.x;
    if (e >= N_EDGES) return;
    int r = ei[e];               // src (row)
    int c = ei[N_EDGES + e];     // dst (col)
    float nrm = g_dinv[r] * g_dinv[c];
    int pos = atomicAdd(&g_cursor[c], 1);
    g_edges[pos] = make_int2(r, __float_as_int(nrm));
}

// ---------------- lin1: h0 = x @ W1 + b1  (f32x2 packed FMA) ------------------
// writes fp32 anchor g_h0 and fp16 copy g_h16A
__global__ void __launch_bounds__(256) k_gemm1(const float* __restrict__ x,
                                               const float* __restrict__ W1,
                                               const float* __restrict__ b1) {
    __shared__ __align__(16) float Ws[32 * 64];     // 8 KB
    __shared__ float xs[256 * 33];                  // 33 KB, padded stride
    __shared__ __align__(16) float bs[64];

    const int tid = threadIdx.x;
    const int row = blockIdx.x * 256 + tid;

    if (tid < 16) {
        *(float4*)&bs[tid * 4] = *(const float4*)&b1[tid * 4];
    }
    __syncthreads();

    unsigned long long acc[32];
#pragma unroll
    for (int p = 0; p < 32; p++)
        acc[p] = *(const unsigned long long*)&bs[2 * p];

    for (int kc = 0; kc < IN_DIM; kc += 32) {
        __syncthreads();
        for (int i = tid; i < 512; i += 256) {
            int kk = i >> 4, j4 = i & 15;
            float4 v = make_float4(0.f, 0.f, 0.f, 0.f);
            if (kc + kk < IN_DIM)
                v = *(const float4*)&W1[(size_t)(kc + kk) * HID + j4 * 4];
            *(float4*)&Ws[kk * 64 + j4 * 4] = v;
        }
        for (int i = tid; i < 2048; i += 256) {
            int r  = i >> 3;
            int c4 = i & 7;
            int col = kc + c4 * 4;
            int grow = blockIdx.x * 256 + r;
            if (grow >= N_NODES) grow = N_NODES - 1;
            float4 v = make_float4(0.f, 0.f, 0.f, 0.f);
            if (col < IN_DIM)
                v = *(const float4*)&x[(size_t)grow * IN_DIM + col];
            float* d = &xs[r * 33 + c4 * 4];
            d[0] = v.x; d[1] = v.y; d[2] = v.z; d[3] = v.w;
        }
        __syncthreads();

#pragma unroll 2
        for (int kk = 0; kk < 32; kk++) {
            float xv = xs[tid * 33 + kk];
            unsigned long long xv2;
            PACK_DUP(xv2, xv);
            const ulonglong2* wr = reinterpret_cast<const ulonglong2*>(&Ws[kk * 64]);
#pragma unroll
            for (int q = 0; q < 16; q++) {
                ulonglong2 w = wr[q];
                FMA2(acc[2 * q],     xv2, w.x);
                FMA2(acc[2 * q + 1], xv2, w.y);
            }
        }
    }

    if (row < N_NODES) {
#pragma unroll
        for (int q = 0; q < 16; q++) {
            float a, b, c, d;
            UNPACK2(a, b, acc[2 * q]);
            UNPACK2(c, d, acc[2 * q + 1]);
            *(float4*)&g_h0[(size_t)row * HID + q * 4] = make_float4(a, b, c, d);
            g_h16A[(size_t)row * HID2 + q * 2 + 0] = __floats2half2_rn(a, b);
            g_h16A[(size_t)row * HID2 + q * 2 + 1] = __floats2half2_rn(c, d);
        }
    }
}

// ---------------- APPNP propagation step (warp-per-node, fp16 gather) ---------
__global__ void __launch_bounds__(256) k_prop(int sin_sel, int sout_sel, int final_step) {
    const __half2* __restrict__ xin = h16buf(sin_sel);
    __half2* __restrict__ xout = h16buf(sout_sel);

    int node = (blockIdx.x * blockDim.x + threadIdx.x) >> 5;
    int lane = threadIdx.x & 31;
    if (node >= N_NODES) return;

    const int beg = g_ptr[node];
    const int end = g_ptr[node + 1];
    const int deg = end - beg;
    const int nfull = deg & ~31;

    float a0x = 0.f, a0y = 0.f, a1x = 0.f, a1y = 0.f;
    float a2x = 0.f, a2y = 0.f, a3x = 0.f, a3y = 0.f;

    int base = beg;
    for (; base < beg + nfull; base += 32) {
        int2 ed = g_edges[base + lane];
#pragma unroll
        for (int j = 0; j < 32; j += 4) {
            int   s0 = __shfl_sync(0xffffffffu, ed.x, j + 0);
            int   s1 = __shfl_sync(0xffffffffu, ed.x, j + 1);
            int   s2 = __shfl_sync(0xffffffffu, ed.x, j + 2);
            int   s3 = __shfl_sync(0xffffffffu, ed.x, j + 3);
            float n0 = __int_as_float(__shfl_sync(0xffffffffu, ed.y, j + 0));
            float n1 = __int_as_float(__shfl_sync(0xffffffffu, ed.y, j + 1));
            float n2 = __int_as_float(__shfl_sync(0xffffffffu, ed.y, j + 2));
            float n3 = __int_as_float(__shfl_sync(0xffffffffu, ed.y, j + 3));
            float2 v0 = __half22float2(xin[(size_t)s0 * HID2 + lane]);
            float2 v1 = __half22float2(xin[(size_t)s1 * HID2 + lane]);
            float2 v2 = __half22float2(xin[(size_t)s2 * HID2 + lane]);
            float2 v3 = __half22float2(xin[(size_t)s3 * HID2 + lane]);
            a0x = fmaf(n0, v0.x, a0x);  a0y = fmaf(n0, v0.y, a0y);
            a1x = fmaf(n1, v1.x, a1x);  a1y = fmaf(n1, v1.y, a1y);
            a2x = fmaf(n2, v2.x, a2x);  a2y = fmaf(n2, v2.y, a2y);
            a3x = fmaf(n3, v3.x, a3x);  a3y = fmaf(n3, v3.y, a3y);
        }
    }

    // remainder (< 32 edges)
    const int rem = deg - nfull;
    if (rem) {
        int idx = base + lane;
        int2 ed = (idx < end) ? g_edges[idx] : make_int2(0, 0);
        for (int j = 0; j < rem; j++) {
            int   src = __shfl_sync(0xffffffffu, ed.x, j);
            float nrm = __int_as_float(__shfl_sync(0xffffffffu, ed.y, j));
            float2 v = __half22float2(xin[(size_t)src * HID2 + lane]);
            a0x = fmaf(nrm, v.x, a0x);
            a0y = fmaf(nrm, v.y, a0y);
        }
    }

    float ax = (a0x + a1x) + (a2x + a3x);
    float ay = (a0y + a1y) + (a2y + a3y);

    // self loop
    float dv = g_dinv[node];
    float sn = dv * dv;
    float2 vs = __half22float2(xin[(size_t)node * HID2 + lane]);
    ax = fmaf(sn, vs.x, ax);
    ay = fmaf(sn, vs.y, ay);

    float2 h0v = *(const float2*)(g_h0 + (size_t)node * HID + lane * 2);
    float ox = 0.9f * ax + 0.1f * h0v.x;
    float oy = 0.9f * ay + 0.1f * h0v.y;

    xout[(size_t)node * HID2 + lane] = __floats2half2_rn(ox, oy);
    if (final_step) {
        float2 o; o.x = ox; o.y = oy;
        *(float2*)(g_hf32 + (size_t)node * HID + lane * 2) = o;
    }
}

// ---------------- BN + lin2 + log_softmax (fused epilogue, reads fp32) --------
__global__ void __launch_bounds__(128) k_epilogue(const float* __restrict__ gamma,
                                                  const float* __restrict__ beta,
                                                  const float* __restrict__ mean,
                                                  const float* __restrict__ var,
                                                  const float* __restrict__ W2,
                                                  const float* __restrict__ b2,
                                                  float* __restrict__ out) {
    __shared__ float sc[HID], sh[HID];
    __shared__ float W2s[HID * OUT_DIM];
    __shared__ float b2s[OUT_DIM];

    const int tid = threadIdx.x;
    if (tid < HID) {
        float s = gamma[tid] * rsqrtf(var[tid] + 1e-5f);
        sc[tid] = s;
        sh[tid] = beta[tid] - mean[tid] * s;
    }
    if (tid < OUT_DIM) b2s[tid] = b2[tid];
    for (int i = tid; i < HID * OUT_DIM; i += 128) W2s[i] = W2[i];
    __syncthreads();

    int node = blockIdx.x * 128 + tid;
    if (node >= N_NODES) return;

    float acc[OUT_DIM];
#pragma unroll
    for (int j = 0; j < OUT_DIM; j++) acc[j] = b2s[j];

    const float* hp = g_hf32 + (size_t)node * HID;
    for (int k = 0; k < HID; k++) {
        float t = fmaf(hp[k], sc[k], sh[k]);
#pragma unroll
        for (int j = 0; j < OUT_DIM; j++)
            acc[j] = fmaf(t, W2s[k * OUT_DIM + j], acc[j]);
    }

    float m = acc[0];
#pragma unroll
    for (int j = 1; j < OUT_DIM; j++) m = fmaxf(m, acc[j]);
    float s = 0.f;
#pragma unroll
    for (int j = 0; j < OUT_DIM; j++) s += expf(acc[j] - m);
    float lse = m + logf(s);

    float* op = out + (size_t)node * OUT_DIM;                              // log_softmax
    float* ep = out + (size_t)N_NODES * OUT_DIM + (size_t)node * OUT_DIM;  // emb
#pragma unroll
    for (int j4 = 0; j4 < OUT_DIM / 4; j4++) {
        float4 e = make_float4(acc[4*j4], acc[4*j4+1], acc[4*j4+2], acc[4*j4+3]);
        float4 o = make_float4(e.x - lse, e.y - lse, e.z - lse, e.w - lse);
        *(float4*)&op[4 * j4] = o;
        *(float4*)&ep[4 * j4] = e;
    }
}

// ---------------- host launcher -----------------------------------------------
extern "C" void kernel_launch(void* const* d_in, const int* in_sizes, int n_in,
                              void* d_out, int out_size) {
    const float* x     = (const float*)d_in[0];
    const int*   ei    = (const int*)d_in[1];     // int64 inputs delivered as int32
    const float* W1    = (const float*)d_in[2];
    const float* b1    = (const float*)d_in[3];
    const float* gamma = (const float*)d_in[4];
    const float* beta  = (const float*)d_in[5];
    const float* mean  = (const float*)d_in[6];
    const float* var   = (const float*)d_in[7];
    const float* W2    = (const float*)d_in[8];
    const float* b2    = (const float*)d_in[9];
    float*       out   = (float*)d_out;

    const int nb_n = (N_NODES + 255) / 256;
    const int nb_e = (N_EDGES + 255) / 256;

    k_zero_counts<<<nb_n, 256>>>();
    k_count<<<nb_e, 256>>>(ei + N_EDGES);     // col = second row of edge_index
    k_dinv<<<nb_n, 256>>>();
    k_scanA<<<NUM_TILES, SCAN_TILE>>>();
    k_scanB<<<1, 128>>>();
    k_scanC<<<nb_n, 256>>>();
    k_scatter<<<nb_e, 256>>>(ei);

    k_gemm1<<<nb_n, 256>>>(x, W1, b1);

    const int prop_blocks = (N_NODES * 32 + 255) / 256;
    for (int s = 0; s < K_STEPS; s++) {
        // even step: A -> B, odd step: B -> A
        k_prop<<<prop_blocks, 256>>>(s & 1, (s & 1) ^ 1, s == K_STEPS - 1);
    }

    k_epilogue<<<(N_NODES + 127) / 128, 128>>>(gamma, beta, mean, var, W2, b2, out);
}

// round 7
// speedup vs baseline: 1.7464x; 1.0158x over previous
#include <cuda_runtime.h>
#include <cuda_fp16.h>
#include <math.h>

#define N_NODES 100000
#define N_EDGES 3200000
#define IN_DIM  500
#define HID     64
#define HID2    (HID / 2)
#define OUT_DIM 40
#define K_STEPS 10
#define SCAN_TILE 1024
#define NUM_TILES ((N_NODES + SCAN_TILE - 1) / SCAN_TILE)   // 98

// ---------------- device scratch (static: no allocations allowed) -------------
__device__ int   g_counts[N_NODES];
__device__ float g_dinv[N_NODES];
__device__ int   g_ptr[N_NODES + 1];
__device__ int   g_cursor[N_NODES];
__device__ int   g_tilesum[NUM_TILES];
__device__ int   g_tileoff[NUM_TILES];
__device__ __align__(16) int2    g_edges[N_EDGES];           // (src, norm-bits), dst-sorted
__device__ __align__(16) float   g_h0[(size_t)N_NODES * HID];    // fp32 anchor
__device__ __align__(16) float   g_hf32[(size_t)N_NODES * HID];  // fp32 final (epilogue)
__device__ __align__(16) __half2 g_h16A[(size_t)N_NODES * HID2]; // fp16 ping
__device__ __align__(16) __half2 g_h16B[(size_t)N_NODES * HID2]; // fp16 pong

__device__ __forceinline__ __half2* h16buf(int s) { return s ? g_h16B : g_h16A; }

// ---------------- f32x2 packed-FMA helpers -----------------------------------
#define FMA2(acc, a, b) \
    asm("fma.rn.f32x2 %0, %1, %2, %0;" : "+l"(acc) : "l"(a), "l"(b))
#define PACK_DUP(dst, x) \
    asm("mov.b64 %0, {%1, %1};" : "=l"(dst) : "f"(x))
#define UNPACK2(lo, hi, v) \
    asm("mov.b64 {%0, %1}, %2;" : "=f"(lo), "=f"(hi) : "l"(v))

// ---------------- CSR build ---------------------------------------------------
__global__ void k_zero_counts() {
    int i = blockIdx.x * blockDim.x + threadIdx.x;
    if (i < N_NODES) g_counts[i] = 0;
}

__global__ void k_count(const int* __restrict__ col) {
    int e = blockIdx.x * blockDim.x + threadIdx.x;
    if (e < N_EDGES) atomicAdd(&g_counts[col[e]], 1);
}

__global__ void k_dinv() {
    int i = blockIdx.x * blockDim.x + threadIdx.x;
    if (i < N_NODES) g_dinv[i] = rsqrtf((float)(g_counts[i] + 1)); // +1 self loop
}

// --- parallel 3-phase exclusive scan of g_counts -> g_ptr / g_cursor ---------
__global__ void __launch_bounds__(SCAN_TILE) k_scanA() {
    __shared__ int s[SCAN_TILE];
    const int t = threadIdx.x;
    const int gid = blockIdx.x * SCAN_TILE + t;
    int v = (gid < N_NODES) ? g_counts[gid] : 0;
    s[t] = v;
    __syncthreads();
#pragma unroll
    for (int off = 1; off < SCAN_TILE; off <<= 1) {
        int u = (t >= off) ? s[t - off] : 0;
        __syncthreads();
        s[t] += u;
        __syncthreads();
    }
    if (gid < N_NODES) g_ptr[gid] = s[t] - v;      // exclusive, tile-local
    if (t == SCAN_TILE - 1) g_tilesum[blockIdx.x] = s[t];
}

__global__ void __launch_bounds__(128) k_scanB() {
    __shared__ int s[128];
    const int t = threadIdx.x;
    int v = (t < NUM_TILES) ? g_tilesum[t] : 0;
    s[t] = v;
    __syncthreads();
#pragma unroll
    for (int off = 1; off < 128; off <<= 1) {
        int u = (t >= off) ? s[t - off] : 0;
        __syncthreads();
        s[t] += u;
        __syncthreads();
    }
    if (t < NUM_TILES) g_tileoff[t] = s[t] - v;
}

__global__ void k_scanC() {
    int i = blockIdx.x * blockDim.x + threadIdx.x;
    if (i < N_NODES) {
        int p = g_ptr[i] + g_tileoff[i >> 10];
        g_ptr[i] = p;
        g_cursor[i] = p;
    }
    if (i == 0) g_ptr[N_NODES] = N_EDGES;
}

__global__ void k_scatter(const int* __restrict__ ei) {
    int e = blockIdx.x * blockDim.x + threadIdx.x;
    if (e >= N_EDGES) return;
    int r = ei[e];               // src (row)
    int c = ei[N_EDGES + e];     // dst (col)
    float nrm = g_dinv[r] * g_dinv[c];
    int pos = atomicAdd(&g_cursor[c], 1);
    g_edges[pos] = make_int2(r, __float_as_int(nrm));
}

// ---------------- lin1: h0 = x @ W1 + b1  (f32x2 packed FMA) ------------------
// writes fp32 anchor g_h0 and fp16 copy g_h16A
__global__ void __launch_bounds__(256) k_gemm1(const float* __restrict__ x,
                                               const float* __restrict__ W1,
                                               const float* __restrict__ b1) {
    __shared__ __align__(16) float Ws[32 * 64];     // 8 KB
    __shared__ float xs[256 * 33];                  // 33 KB, padded stride
    __shared__ __align__(16) float bs[64];

    const int tid = threadIdx.x;
    const int row = blockIdx.x * 256 + tid;

    if (tid < 16) {
        *(float4*)&bs[tid * 4] = *(const float4*)&b1[tid * 4];
    }
    __syncthreads();

    unsigned long long acc[32];
#pragma unroll
    for (int p = 0; p < 32; p++)
        acc[p] = *(const unsigned long long*)&bs[2 * p];

    for (int kc = 0; kc < IN_DIM; kc += 32) {
        __syncthreads();
        for (int i = tid; i < 512; i += 256) {
            int kk = i >> 4, j4 = i & 15;
            float4 v = make_float4(0.f, 0.f, 0.f, 0.f);
            if (kc + kk < IN_DIM)
                v = *(const float4*)&W1[(size_t)(kc + kk) * HID + j4 * 4];
            *(float4*)&Ws[kk * 64 + j4 * 4] = v;
        }
        for (int i = tid; i < 2048; i += 256) {
            int r  = i >> 3;
            int c4 = i & 7;
            int col = kc + c4 * 4;
            int grow = blockIdx.x * 256 + r;
            if (grow >= N_NODES) grow = N_NODES - 1;
            float4 v = make_float4(0.f, 0.f, 0.f, 0.f);
            if (col < IN_DIM)
                v = *(const float4*)&x[(size_t)grow * IN_DIM + col];
            float* d = &xs[r * 33 + c4 * 4];
            d[0] = v.x; d[1] = v.y; d[2] = v.z; d[3] = v.w;
        }
        __syncthreads();

#pragma unroll 2
        for (int kk = 0; kk < 32; kk++) {
            float xv = xs[tid * 33 + kk];
            unsigned long long xv2;
            PACK_DUP(xv2, xv);
            const ulonglong2* wr = reinterpret_cast<const ulonglong2*>(&Ws[kk * 64]);
#pragma unroll
            for (int q = 0; q < 16; q++) {
                ulonglong2 w = wr[q];
                FMA2(acc[2 * q],     xv2, w.x);
                FMA2(acc[2 * q + 1], xv2, w.y);
            }
        }
    }

    if (row < N_NODES) {
#pragma unroll
        for (int q = 0; q < 16; q++) {
            float a, b, c, d;
            UNPACK2(a, b, acc[2 * q]);
            UNPACK2(c, d, acc[2 * q + 1]);
            *(float4*)&g_h0[(size_t)row * HID + q * 4] = make_float4(a, b, c, d);
            g_h16A[(size_t)row * HID2 + q * 2 + 0] = __floats2half2_rn(a, b);
            g_h16A[(size_t)row * HID2 + q * 2 + 1] = __floats2half2_rn(c, d);
        }
    }
}

// ---------------- APPNP propagation (warp-per-node, 2 edges/iteration) --------
// Lanes 0-15 process edge j (dims lane*4..lane*4+3 via one uint2 = 2 half2);
// lanes 16-31 process edge j+half. Cross-half combine via shfl_down(16).
__global__ void __launch_bounds__(256) k_prop(int sin_sel, int sout_sel, int final_step) {
    const __half2* __restrict__ xin = h16buf(sin_sel);
    __half2* __restrict__ xout = h16buf(sout_sel);

    const int node = (blockIdx.x * blockDim.x + threadIdx.x) >> 5;
    const int lane = threadIdx.x & 31;
    if (node >= N_NODES) return;

    const int beg = g_ptr[node];
    const int end = g_ptr[node + 1];
    const int deg = end - beg;
    const int nfull = deg & ~31;
    const int sub = lane & 15;                 // dim group within half-warp
    const int hi16 = lane & 16;                // 0 for low half, 16 for high half

    float aA0 = 0.f, aA1 = 0.f, aA2 = 0.f, aA3 = 0.f;   // even pairs
    float aB0 = 0.f, aB1 = 0.f, aB2 = 0.f, aB3 = 0.f;   // odd pairs

    int base = beg;
    for (; base < beg + nfull; base += 32) {
        int2 ed = g_edges[base + lane];
#pragma unroll
        for (int j = 0; j < 16; j += 2) {
            int   sl0 = j + hi16;
            int   sl1 = j + 1 + hi16;
            int   s0  = __shfl_sync(0xffffffffu, ed.x, sl0);
            int   s1  = __shfl_sync(0xffffffffu, ed.x, sl1);
            float n0  = __int_as_float(__shfl_sync(0xffffffffu, ed.y, sl0));
            float n1  = __int_as_float(__shfl_sync(0xffffffffu, ed.y, sl1));
            uint2 v0  = ((const uint2*)(xin + (size_t)s0 * HID2))[sub];
            uint2 v1  = ((const uint2*)(xin + (size_t)s1 * HID2))[sub];
            float2 f00 = __half22float2(*(__half2*)&v0.x);
            float2 f01 = __half22float2(*(__half2*)&v0.y);
            float2 f10 = __half22float2(*(__half2*)&v1.x);
            float2 f11 = __half22float2(*(__half2*)&v1.y);
            aA0 = fmaf(n0, f00.x, aA0);  aA1 = fmaf(n0, f00.y, aA1);
            aA2 = fmaf(n0, f01.x, aA2);  aA3 = fmaf(n0, f01.y, aA3);
            aB0 = fmaf(n1, f10.x, aB0);  aB1 = fmaf(n1, f10.y, aB1);
            aB2 = fmaf(n1, f11.x, aB2);  aB3 = fmaf(n1, f11.y, aB3);
        }
    }

    // remainder (< 32 edges): zero-padded pair loop, half = ceil(rem/2)
    const int rem = deg - nfull;
    if (rem) {
        int idx = base + lane;
        int2 ed = (idx < end) ? g_edges[idx] : make_int2(0, 0);  // nrm=0 pad
        const int half = (rem + 1) >> 1;
        const int hoff = hi16 ? half : 0;
        for (int j = 0; j < half; j++) {
            int   sl = j + hoff;
            int   s  = __shfl_sync(0xffffffffu, ed.x, sl);
            float n  = __int_as_float(__shfl_sync(0xffffffffu, ed.y, sl));
            uint2 v  = ((const uint2*)(xin + (size_t)s * HID2))[sub];
            float2 f0 = __half22float2(*(__half2*)&v.x);
            float2 f1 = __half22float2(*(__half2*)&v.y);
            aA0 = fmaf(n, f0.x, aA0);  aA1 = fmaf(n, f0.y, aA1);
            aA2 = fmaf(n, f1.x, aA2);  aA3 = fmaf(n, f1.y, aA3);
        }
    }

    float a0 = aA0 + aB0, a1 = aA1 + aB1, a2 = aA2 + aB2, a3 = aA3 + aB3;
    // combine high half into low half
    a0 += __shfl_down_sync(0xffffffffu, a0, 16);
    a1 += __shfl_down_sync(0xffffffffu, a1, 16);
    a2 += __shfl_down_sync(0xffffffffu, a2, 16);
    a3 += __shfl_down_sync(0xffffffffu, a3, 16);

    if (lane < 16) {
        // self loop
        float dv = g_dinv[node];
        float sn = dv * dv;
        uint2 sv = ((const uint2*)(xin + (size_t)node * HID2))[sub];
        float2 s0 = __half22float2(*(__half2*)&sv.x);
        float2 s1 = __half22float2(*(__half2*)&sv.y);
        a0 = fmaf(sn, s0.x, a0);  a1 = fmaf(sn, s0.y, a1);
        a2 = fmaf(sn, s1.x, a2);  a3 = fmaf(sn, s1.y, a3);

        float4 h0v = ((const float4*)(g_h0 + (size_t)node * HID))[sub];
        float o0 = 0.9f * a0 + 0.1f * h0v.x;
        float o1 = 0.9f * a1 + 0.1f * h0v.y;
        float o2 = 0.9f * a2 + 0.1f * h0v.z;
        float o3 = 0.9f * a3 + 0.1f * h0v.w;

        __half2 p0 = __floats2half2_rn(o0, o1);
        __half2 p1 = __floats2half2_rn(o2, o3);
        uint2 ov;
        ov.x = *(unsigned*)&p0;
        ov.y = *(unsigned*)&p1;
        ((uint2*)(xout + (size_t)node * HID2))[sub] = ov;
        if (final_step) {
            ((float4*)(g_hf32 + (size_t)node * HID))[sub] = make_float4(o0, o1, o2, o3);
        }
    }
}

// ---------------- BN + lin2 + log_softmax (fused epilogue, reads fp32) --------
__global__ void __launch_bounds__(128) k_epilogue(const float* __restrict__ gamma,
                                                  const float* __restrict__ beta,
                                                  const float* __restrict__ mean,
                                                  const float* __restrict__ var,
                                                  const float* __restrict__ W2,
                                                  const float* __restrict__ b2,
                                                  float* __restrict__ out) {
    __shared__ float sc[HID], sh[HID];
    __shared__ float W2s[HID * OUT_DIM];
    __shared__ float b2s[OUT_DIM];

    const int tid = threadIdx.x;
    if (tid < HID) {
        float s = gamma[tid] * rsqrtf(var[tid] + 1e-5f);
        sc[tid] = s;
        sh[tid] = beta[tid] - mean[tid] * s;
    }
    if (tid < OUT_DIM) b2s[tid] = b2[tid];
    for (int i = tid; i < HID * OUT_DIM; i += 128) W2s[i] = W2[i];
    __syncthreads();

    int node = blockIdx.x * 128 + tid;
    if (node >= N_NODES) return;

    float acc[OUT_DIM];
#pragma unroll
    for (int j = 0; j < OUT_DIM; j++) acc[j] = b2s[j];

    const float* hp = g_hf32 + (size_t)node * HID;
    for (int k = 0; k < HID; k++) {
        float t = fmaf(hp[k], sc[k], sh[k]);
#pragma unroll
        for (int j = 0; j < OUT_DIM; j++)
            acc[j] = fmaf(t, W2s[k * OUT_DIM + j], acc[j]);
    }

    float m = acc[0];
#pragma unroll
    for (int j = 1; j < OUT_DIM; j++) m = fmaxf(m, acc[j]);
    float s = 0.f;
#pragma unroll
    for (int j = 0; j < OUT_DIM; j++) s += expf(acc[j] - m);
    float lse = m + logf(s);

    float* op = out + (size_t)node * OUT_DIM;                              // log_softmax
    float* ep = out + (size_t)N_NODES * OUT_DIM + (size_t)node * OUT_DIM;  // emb
#pragma unroll
    for (int j4 = 0; j4 < OUT_DIM / 4; j4++) {
        float4 e = make_float4(acc[4*j4], acc[4*j4+1], acc[4*j4+2], acc[4*j4+3]);
        float4 o = make_float4(e.x - lse, e.y - lse, e.z - lse, e.w - lse);
        *(float4*)&op[4 * j4] = o;
        *(float4*)&ep[4 * j4] = e;
    }
}

// ---------------- host launcher -----------------------------------------------
extern "C" void kernel_launch(void* const* d_in, const int* in_sizes, int n_in,
                              void* d_out, int out_size) {
    const float* x     = (const float*)d_in[0];
    const int*   ei    = (const int*)d_in[1];     // int64 inputs delivered as int32
    const float* W1    = (const float*)d_in[2];
    const float* b1    = (const float*)d_in[3];
    const float* gamma = (const float*)d_in[4];
    const float* beta  = (const float*)d_in[5];
    const float* mean  = (const float*)d_in[6];
    const float* var   = (const float*)d_in[7];
    const float* W2    = (const float*)d_in[8];
    const float* b2    = (const float*)d_in[9];
    float*       out   = (float*)d_out;

    const int nb_n = (N_NODES + 255) / 256;
    const int nb_e = (N_EDGES + 255) / 256;

    k_zero_counts<<<nb_n, 256>>>();
    k_count<<<nb_e, 256>>>(ei + N_EDGES);     // col = second row of edge_index
    k_dinv<<<nb_n, 256>>>();
    k_scanA<<<NUM_TILES, SCAN_TILE>>>();
    k_scanB<<<1, 128>>>();
    k_scanC<<<nb_n, 256>>>();
    k_scatter<<<nb_e, 256>>>(ei);

    k_gemm1<<<nb_n, 256>>>(x, W1, b1);

    const int prop_blocks = (N_NODES * 32 + 255) / 256;
    for (int s = 0; s < K_STEPS; s++) {
        // even step: A -> B, odd step: B -> A
        k_prop<<<prop_blocks, 256>>>(s & 1, (s & 1) ^ 1, s == K_STEPS - 1);
    }

    k_epilogue<<<(N_NODES + 127) / 128, 128>>>(gamma, beta, mean, var, W2, b2, out);
}